// round 15
// baseline (speedup 1.0000x reference)
#include <cuda_runtime.h>
#include <cuda_fp16.h>
#include <cstdint>

#define MAX_NODES 100000
#define MAX_EDGES 1250000
#define HID 64

// Scratch (allocation-free: __device__ globals)
__device__ int     g_cnt[MAX_NODES];
__device__ int     g_rowstart[MAX_NODES];
__device__ int     g_cursor[MAX_NODES];
__device__ int     g_total;
__device__ float   g_dinv[MAX_NODES];
__device__ int     g_psrc[MAX_EDGES];
__device__ __half2 g_hh[(size_t)MAX_NODES * (HID / 2)];    // dinv[s]*h[s], fp16 gather table
__device__ __half2 g_out1h[(size_t)MAX_NODES * (HID / 2)]; // layer-1 output, fp16
__device__ uint2   g_Wf1[8 * 8 * 32];   // W1 fragments
__device__ uint2   g_Wf2[4 * 8 * 32];   // W2 fragments

// ---------------------------------------------------------------------------
// Fused: pack W fragments (idx < 3072) + zero g_cnt (idx < n) + zero g_total
// ---------------------------------------------------------------------------
__global__ void k_pack_zero(const float* __restrict__ W1, const float* __restrict__ W2, int n) {
    int idx = blockIdx.x * blockDim.x + threadIdx.x;
    if (idx < n) g_cnt[idx] = 0;
    if (idx == 0) g_total = 0;
    if (idx < 3072) {
        const float* W;
        uint2* dstf;
        int rel;
        if (idx < 2048) { W = W1; dstf = g_Wf1; rel = idx; }
        else            { W = W2; dstf = g_Wf2; rel = idx - 2048; }
        const int lane  = rel & 31;
        const int nt    = (rel >> 5) & 7;
        const int kstep = rel >> 8;
        const int nn = nt * 8 + (lane >> 2);
        const int k0 = kstep * 16 + (lane & 3) * 2;
        __half2 b0 = __floats2half2_rn(__ldg(&W[(size_t)k0 * 64 + nn]),
                                       __ldg(&W[(size_t)(k0 + 1) * 64 + nn]));
        __half2 b1 = __floats2half2_rn(__ldg(&W[(size_t)(k0 + 8) * 64 + nn]),
                                       __ldg(&W[(size_t)(k0 + 9) * 64 + nn]));
        uint2 u;
        u.x = *reinterpret_cast<uint32_t*>(&b0);
        u.y = *reinterpret_cast<uint32_t*>(&b1);
        dstf[rel] = u;
    }
}

// ---------------------------------------------------------------------------
// CSR build: count -> rowstart (atomic bump, fused dinv+cursor) -> scatter
// ---------------------------------------------------------------------------
__global__ void k_count(const int* __restrict__ dst, int nE) {
    int e = blockIdx.x * blockDim.x + threadIdx.x;
    if (e < nE) atomicAdd(&g_cnt[__ldg(&dst[e])], 1);
}

__global__ void __launch_bounds__(256) k_rowstart(int n) {
    __shared__ int wsum[8];
    __shared__ int sbase;
    const int tid  = threadIdx.x;
    const int lane = tid & 31;
    const int wid  = tid >> 5;
    const int i = blockIdx.x * 256 + tid;

    int c = (i < n) ? g_cnt[i] : 0;
    int scan = c;
#pragma unroll
    for (int off = 1; off < 32; off <<= 1) {
        int v = __shfl_up_sync(0xffffffffu, scan, off);
        if (lane >= off) scan += v;
    }
    if (lane == 31) wsum[wid] = scan;
    __syncthreads();
    if (wid == 0) {
        int w = (lane < 8) ? wsum[lane] : 0;
        int ws = w;
#pragma unroll
        for (int off = 1; off < 8; off <<= 1) {
            int v = __shfl_up_sync(0xffffffffu, ws, off);
            if (lane >= off) ws += v;
        }
        if (lane < 8) wsum[lane] = ws - w;              // exclusive warp offsets
        if (lane == 7) sbase = atomicAdd(&g_total, ws); // ws @lane7 = block total
    }
    __syncthreads();
    if (i < n) {
        const int rs = sbase + wsum[wid] + scan - c;
        g_rowstart[i] = rs;
        g_cursor[i]   = rs;
        g_dinv[i]     = rsqrtf((float)c + 1.0f);
    }
}

__global__ void k_scatter(const int* __restrict__ src, const int* __restrict__ dst, int nE) {
    int e = blockIdx.x * blockDim.x + threadIdx.x;
    if (e < nE) {
        int d = __ldg(&dst[e]);
        int pos = atomicAdd(&g_cursor[d], 1);
        g_psrc[pos] = __ldg(&src[e]);
    }
}

// ---------------------------------------------------------------------------
// fp16 HMMA GEMM: h = act(A) @ W, mma.sync.m16n8k16 f32.f16.f16.f32.
// B fragments read directly from global (lane-indexed, L1-broadcast across
// all warps/CTAs) -> smem = A tile only -> 6 CTAs/SM instead of 4.
// Epilogue: hh = fp16(h*dinv) ; aout = bias + (h*dinv)*dinv.
// ---------------------------------------------------------------------------
#define ASTR 136   // halves per A row in smem

__device__ __forceinline__ void mma_f16(float* c,
                                        uint32_t a0, uint32_t a1, uint32_t a2, uint32_t a3,
                                        uint32_t b0, uint32_t b1) {
    asm volatile("mma.sync.aligned.m16n8k16.row.col.f32.f16.f16.f32 "
                 "{%0,%1,%2,%3}, {%4,%5,%6,%7}, {%8,%9}, {%0,%1,%2,%3};"
                 : "+f"(c[0]), "+f"(c[1]), "+f"(c[2]), "+f"(c[3])
                 : "r"(a0), "r"(a1), "r"(a2), "r"(a3), "r"(b0), "r"(b1));
}

template<int KDIM, bool RELU_IN, bool IN_HALF, bool OUT_HALF>
__global__ void __launch_bounds__(256) k_gemm_hmma(const void* __restrict__ Ain,
                                                   const uint2* __restrict__ Wf,
                                                   const float* __restrict__ bias,
                                                   __half2* __restrict__ hout,
                                                   void* __restrict__ aout,
                                                   int M)
{
    extern __shared__ char smem[];
    __half* As = reinterpret_cast<__half*>(smem);   // 128 x ASTR halves

    const int tid  = threadIdx.x;
    const int lane = tid & 31;
    const int warp = tid >> 5;
    const int row0 = blockIdx.x * 128;

    const int lrow = tid >> 1;
    const int arow = min(row0 + lrow, M - 1);
    if (!IN_HALF) {
        const float* A = (const float*)Ain;
        const int lc4 = (tid & 1) * 4;
#pragma unroll
        for (int k0 = 0; k0 < KDIM; k0 += 8) {
            float4 av = *reinterpret_cast<const float4*>(A + (size_t)arow * KDIM + k0 + lc4);
            if (RELU_IN) {
                av.x = fmaxf(av.x, 0.0f); av.y = fmaxf(av.y, 0.0f);
                av.z = fmaxf(av.z, 0.0f); av.w = fmaxf(av.w, 0.0f);
            }
            __half2 h0 = __floats2half2_rn(av.x, av.y);
            __half2 h1 = __floats2half2_rn(av.z, av.w);
            uint2 u;
            u.x = *reinterpret_cast<uint32_t*>(&h0);
            u.y = *reinterpret_cast<uint32_t*>(&h1);
            *reinterpret_cast<uint2*>(As + lrow * ASTR + k0 + lc4) = u;
        }
    } else {
        const __half* A = (const __half*)Ain;
        const int lch = (tid & 1) * (KDIM / 2);
        const __half2 z2 = __float2half2_rn(0.0f);
#pragma unroll
        for (int k0 = 0; k0 < KDIM / 2; k0 += 8) {
            uint4 v = *reinterpret_cast<const uint4*>(A + (size_t)arow * KDIM + lch + k0);
            if (RELU_IN) {
                __half2* hv = reinterpret_cast<__half2*>(&v);
#pragma unroll
                for (int j = 0; j < 4; j++) hv[j] = __hmax2(hv[j], z2);
            }
            *reinterpret_cast<uint4*>(As + lrow * ASTR + lch + k0) = v;
        }
    }
    __syncthreads();

    float acc[8][4];
#pragma unroll
    for (int nt = 0; nt < 8; nt++)
#pragma unroll
        for (int j = 0; j < 4; j++) acc[nt][j] = 0.0f;

    const int r  = lane >> 2;
    const int c2 = (lane & 3) * 2;
    const __half* abase = As + (warp * 16 + r) * ASTR + c2;

#pragma unroll
    for (int ks = 0; ks < KDIM / 16; ks++) {
        const int k0 = ks * 16;
        uint32_t a0 = *reinterpret_cast<const uint32_t*>(abase + k0);
        uint32_t a1 = *reinterpret_cast<const uint32_t*>(abase + k0 + 8 * ASTR);
        uint32_t a2 = *reinterpret_cast<const uint32_t*>(abase + k0 + 8);
        uint32_t a3 = *reinterpret_cast<const uint32_t*>(abase + k0 + 8 * ASTR + 8);
        const uint2* bbase = Wf + ks * 256 + lane;
#pragma unroll
        for (int nt = 0; nt < 8; nt++) {
            uint2 b = __ldg(bbase + nt * 32);
            mma_f16(acc[nt], a0, a1, a2, a3, b.x, b.y);
        }
    }

    const int mr0 = row0 + warp * 16 + r;
    const int mr1 = mr0 + 8;
    const float dv0 = (mr0 < M) ? g_dinv[mr0] : 0.0f;
    const float dv1 = (mr1 < M) ? g_dinv[mr1] : 0.0f;

#pragma unroll
    for (int nt = 0; nt < 8; nt++) {
        const int col = nt * 8 + c2;
        const float2 bv = *reinterpret_cast<const float2*>(bias + col);
        if (mr0 < M) {
            const float hs0 = acc[nt][0] * dv0, hs1 = acc[nt][1] * dv0;
            hout[(size_t)mr0 * (HID / 2) + (col >> 1)] = __floats2half2_rn(hs0, hs1);
            const float o0 = bv.x + hs0 * dv0, o1 = bv.y + hs1 * dv0;
            if (OUT_HALF)
                ((__half2*)aout)[(size_t)mr0 * (HID / 2) + (col >> 1)] = __floats2half2_rn(o0, o1);
            else
                *reinterpret_cast<float2*>((float*)aout + (size_t)mr0 * HID + col) = make_float2(o0, o1);
        }
        if (mr1 < M) {
            const float hs2 = acc[nt][2] * dv1, hs3 = acc[nt][3] * dv1;
            hout[(size_t)mr1 * (HID / 2) + (col >> 1)] = __floats2half2_rn(hs2, hs3);
            const float o2 = bv.x + hs2 * dv1, o3 = bv.y + hs3 * dv1;
            if (OUT_HALF)
                ((__half2*)aout)[(size_t)mr1 * (HID / 2) + (col >> 1)] = __floats2half2_rn(o2, o3);
            else
                *reinterpret_cast<float2*>((float*)aout + (size_t)mr1 * HID + col) = make_float2(o2, o3);
        }
    }
}

// ---------------------------------------------------------------------------
// Pull-mode aggregation: out[d] += dinv[d] * sum_{s in N(d)} hh[s]
// 8 lanes/node; 16B fp16 gathers; two independent half-segment chains (R11).
// ---------------------------------------------------------------------------
__device__ __forceinline__ void acc_16B(float2* acc, uint4 v) {
    float2 f0 = __half22float2(*reinterpret_cast<__half2*>(&v.x));
    float2 f1 = __half22float2(*reinterpret_cast<__half2*>(&v.y));
    float2 f2 = __half22float2(*reinterpret_cast<__half2*>(&v.z));
    float2 f3 = __half22float2(*reinterpret_cast<__half2*>(&v.w));
    acc[0].x += f0.x; acc[0].y += f0.y;
    acc[1].x += f1.x; acc[1].y += f1.y;
    acc[2].x += f2.x; acc[2].y += f2.y;
    acc[3].x += f3.x; acc[3].y += f3.y;
}

template<bool HALF_OUT>
__global__ void __launch_bounds__(256) k_node_agg(const __half2* __restrict__ hh,
                                                  void* __restrict__ out,
                                                  int n)
{
    const int gid  = blockIdx.x * blockDim.x + threadIdx.x;
    const int node = gid >> 3;
    const int l    = gid & 7;
    if (node >= n) return;

    const int start = __ldg(&g_rowstart[node]);
    const int cn    = __ldg(&g_cnt[node]);
    const int half  = cn >> 1;

    float2 accA[4] = {{0,0},{0,0},{0,0},{0,0}};
    float2 accB[4] = {{0,0},{0,0},{0,0},{0,0}};

    const int a0 = start;
    const int b0 = start + half;
    for (int k = 0; k < half; k++) {
        const int sa = __ldg(&g_psrc[a0 + k]);
        const int sb = __ldg(&g_psrc[b0 + k]);
        const uint4 va = __ldg(reinterpret_cast<const uint4*>(hh + (size_t)sa * (HID / 2)) + l);
        const uint4 vb = __ldg(reinterpret_cast<const uint4*>(hh + (size_t)sb * (HID / 2)) + l);
        acc_16B(accA, va);
        acc_16B(accB, vb);
    }
    if (cn & 1) {
        const int s = __ldg(&g_psrc[start + cn - 1]);
        const uint4 v = __ldg(reinterpret_cast<const uint4*>(hh + (size_t)s * (HID / 2)) + l);
        acc_16B(accA, v);
    }

    const float dd = __ldg(&g_dinv[node]);
    if (HALF_OUT) {
        uint4* p = reinterpret_cast<uint4*>((__half2*)out + (size_t)node * (HID / 2)) + l;
        uint4 o = *p;
        __half2* oh = reinterpret_cast<__half2*>(&o);
#pragma unroll
        for (int j = 0; j < 4; j++) {
            float2 f = __half22float2(oh[j]);
            f.x += dd * (accA[j].x + accB[j].x);
            f.y += dd * (accA[j].y + accB[j].y);
            oh[j] = __floats2half2_rn(f.x, f.y);
        }
        *p = o;
    } else {
        float* p = (float*)out + (size_t)node * HID + l * 8;
        float4 o0 = *reinterpret_cast<float4*>(p);
        float4 o1 = *reinterpret_cast<float4*>(p + 4);
        o0.x += dd * (accA[0].x + accB[0].x);
        o0.y += dd * (accA[0].y + accB[0].y);
        o0.z += dd * (accA[1].x + accB[1].x);
        o0.w += dd * (accA[1].y + accB[1].y);
        o1.x += dd * (accA[2].x + accB[2].x);
        o1.y += dd * (accA[2].y + accB[2].y);
        o1.z += dd * (accA[3].x + accB[3].x);
        o1.w += dd * (accA[3].y + accB[3].y);
        *reinterpret_cast<float4*>(p)     = o0;
        *reinterpret_cast<float4*>(p + 4) = o1;
    }
}

// ---------------------------------------------------------------------------
// Launch
// ---------------------------------------------------------------------------
extern "C" void kernel_launch(void* const* d_in, const int* in_sizes, int n_in,
                              void* d_out, int out_size)
{
    const float* x  = (const float*)d_in[0];
    const int*   ei = (const int*)d_in[1];   // edge_index is int32
    const float* W1 = (const float*)d_in[2];
    const float* b1 = (const float*)d_in[3];
    const float* W2 = (const float*)d_in[4];
    const float* b2 = (const float*)d_in[5];
    float* out = (float*)d_out;

    const int n  = in_sizes[0] / 128;
    const int nE = in_sizes[1] / 2;
    const int* src = ei;
    const int* dst = ei + nE;

    __half2 *hh = nullptr, *out1h = nullptr;
    uint2 *wf1 = nullptr, *wf2 = nullptr;
    cudaGetSymbolAddress((void**)&hh, g_hh);
    cudaGetSymbolAddress((void**)&out1h, g_out1h);
    cudaGetSymbolAddress((void**)&wf1, g_Wf1);
    cudaGetSymbolAddress((void**)&wf2, g_Wf2);

    const int nb_nodes = (n + 255) / 256;
    const int nb_edges = (nE + 255) / 256;
    const int nb_agg   = (n * 8 + 255) / 256;
    const int nb_gemm  = (n + 127) / 128;

    const int smem_g = 128 * ASTR * 2;   // 34816 (A tile only)
    cudaFuncSetAttribute(k_gemm_hmma<128, false, false, true>,
                         cudaFuncAttributeMaxDynamicSharedMemorySize, smem_g);
    cudaFuncSetAttribute(k_gemm_hmma<64, true, true, false>,
                         cudaFuncAttributeMaxDynamicSharedMemorySize, smem_g);

    // Fused W packing + zeroing, then CSR build (count -> rowstart -> scatter)
    k_pack_zero<<<nb_nodes, 256>>>(W1, W2, n);
    k_count<<<nb_edges, 256>>>(dst, nE);
    k_rowstart<<<nb_nodes, 256>>>(n);
    k_scatter<<<nb_edges, 256>>>(src, dst, nE);

    // Layer 1 (out1 in fp16)
    k_gemm_hmma<128, false, false, true><<<nb_gemm, 256, smem_g>>>(x, wf1, b1, hh, out1h, n);
    k_node_agg<true><<<nb_agg, 256>>>(hh, out1h, n);

    // Layer 2 (fp16 A input, ReLU fused; fp32 output straight to d_out)
    k_gemm_hmma<64, true, true, false><<<nb_gemm, 256, smem_g>>>(out1h, wf2, b2, hh, out, n);
    k_node_agg<false><<<nb_agg, 256>>>(hh, out, n);
}

// round 16
// speedup vs baseline: 1.4418x; 1.4418x over previous
#include <cuda_runtime.h>
#include <cuda_fp16.h>
#include <cstdint>

#define MAX_NODES 100000
#define MAX_EDGES 1250000
#define HID 64

// Scratch (allocation-free: __device__ globals)
__device__ int     g_cnt[MAX_NODES];
__device__ int     g_rowstart[MAX_NODES];
__device__ int     g_cursor[MAX_NODES];
__device__ int     g_total;
__device__ float   g_dinv[MAX_NODES];
__device__ int     g_psrc[MAX_EDGES];
__device__ __half2 g_hh[(size_t)MAX_NODES * (HID / 2)];    // dinv[s]*h[s], fp16 gather table
__device__ __half2 g_out1h[(size_t)MAX_NODES * (HID / 2)]; // layer-1 output, fp16
__device__ uint2   g_Wf1[8 * 8 * 32];   // W1 fragments
__device__ uint2   g_Wf2[4 * 8 * 32];   // W2 fragments

// ---------------------------------------------------------------------------
// Fused: pack W fragments (idx < 3072) + zero g_cnt (idx < n) + zero g_total
// ---------------------------------------------------------------------------
__global__ void k_pack_zero(const float* __restrict__ W1, const float* __restrict__ W2, int n) {
    int idx = blockIdx.x * blockDim.x + threadIdx.x;
    if (idx < n) g_cnt[idx] = 0;
    if (idx == 0) g_total = 0;
    if (idx < 3072) {
        const float* W;
        uint2* dstf;
        int rel;
        if (idx < 2048) { W = W1; dstf = g_Wf1; rel = idx; }
        else            { W = W2; dstf = g_Wf2; rel = idx - 2048; }
        const int lane  = rel & 31;
        const int nt    = (rel >> 5) & 7;
        const int kstep = rel >> 8;
        const int nn = nt * 8 + (lane >> 2);
        const int k0 = kstep * 16 + (lane & 3) * 2;
        __half2 b0 = __floats2half2_rn(__ldg(&W[(size_t)k0 * 64 + nn]),
                                       __ldg(&W[(size_t)(k0 + 1) * 64 + nn]));
        __half2 b1 = __floats2half2_rn(__ldg(&W[(size_t)(k0 + 8) * 64 + nn]),
                                       __ldg(&W[(size_t)(k0 + 9) * 64 + nn]));
        uint2 u;
        u.x = *reinterpret_cast<uint32_t*>(&b0);
        u.y = *reinterpret_cast<uint32_t*>(&b1);
        dstf[rel] = u;
    }
}

// ---------------------------------------------------------------------------
// CSR build: count -> rowstart (atomic bump, fused dinv+cursor) -> scatter
// ---------------------------------------------------------------------------
__global__ void k_count(const int* __restrict__ dst, int nE) {
    int e = blockIdx.x * blockDim.x + threadIdx.x;
    if (e < nE) atomicAdd(&g_cnt[__ldg(&dst[e])], 1);
}

__global__ void __launch_bounds__(256) k_rowstart(int n) {
    __shared__ int wsum[8];
    __shared__ int sbase;
    const int tid  = threadIdx.x;
    const int lane = tid & 31;
    const int wid  = tid >> 5;
    const int i = blockIdx.x * 256 + tid;

    int c = (i < n) ? g_cnt[i] : 0;
    int scan = c;
#pragma unroll
    for (int off = 1; off < 32; off <<= 1) {
        int v = __shfl_up_sync(0xffffffffu, scan, off);
        if (lane >= off) scan += v;
    }
    if (lane == 31) wsum[wid] = scan;
    __syncthreads();
    if (wid == 0) {
        int w = (lane < 8) ? wsum[lane] : 0;
        int ws = w;
#pragma unroll
        for (int off = 1; off < 8; off <<= 1) {
            int v = __shfl_up_sync(0xffffffffu, ws, off);
            if (lane >= off) ws += v;
        }
        if (lane < 8) wsum[lane] = ws - w;              // exclusive warp offsets
        if (lane == 7) sbase = atomicAdd(&g_total, ws); // ws @lane7 = block total
    }
    __syncthreads();
    if (i < n) {
        const int rs = sbase + wsum[wid] + scan - c;
        g_rowstart[i] = rs;
        g_cursor[i]   = rs;
        g_dinv[i]     = rsqrtf((float)c + 1.0f);
    }
}

__global__ void k_scatter(const int* __restrict__ src, const int* __restrict__ dst, int nE) {
    int e = blockIdx.x * blockDim.x + threadIdx.x;
    if (e < nE) {
        int d = __ldg(&dst[e]);
        int pos = atomicAdd(&g_cursor[d], 1);
        g_psrc[pos] = __ldg(&src[e]);
    }
}

// ---------------------------------------------------------------------------
// fp16 HMMA GEMM: h = act(A) @ W, mma.sync.m16n8k16 f32.f16.f16.f32.
// Output: hh = fp16(h*dinv) ONLY (self+bias init now folded into agg).
// ---------------------------------------------------------------------------
#define ASTR 136   // halves per A row in smem

__device__ __forceinline__ void mma_f16(float* c,
                                        uint32_t a0, uint32_t a1, uint32_t a2, uint32_t a3,
                                        uint32_t b0, uint32_t b1) {
    asm volatile("mma.sync.aligned.m16n8k16.row.col.f32.f16.f16.f32 "
                 "{%0,%1,%2,%3}, {%4,%5,%6,%7}, {%8,%9}, {%0,%1,%2,%3};"
                 : "+f"(c[0]), "+f"(c[1]), "+f"(c[2]), "+f"(c[3])
                 : "r"(a0), "r"(a1), "r"(a2), "r"(a3), "r"(b0), "r"(b1));
}

template<int KDIM, bool RELU_IN, bool IN_HALF>
__global__ void __launch_bounds__(256) k_gemm_hmma(const void* __restrict__ Ain,
                                                   const uint2* __restrict__ Wf,
                                                   __half2* __restrict__ hout,
                                                   int M)
{
    extern __shared__ char smem[];
    __half* As = reinterpret_cast<__half*>(smem);                 // 128 x ASTR halves
    uint2*  Bf = reinterpret_cast<uint2*>(smem + 128 * ASTR * 2); // (KDIM/16)*256

    const int tid  = threadIdx.x;
    const int lane = tid & 31;
    const int warp = tid >> 5;
    const int row0 = blockIdx.x * 128;

    for (int i = tid; i < (KDIM / 16) * 256; i += 256) Bf[i] = Wf[i];

    const int lrow = tid >> 1;
    const int arow = min(row0 + lrow, M - 1);
    if (!IN_HALF) {
        const float* A = (const float*)Ain;
        const int lc4 = (tid & 1) * 4;
#pragma unroll
        for (int k0 = 0; k0 < KDIM; k0 += 8) {
            float4 av = *reinterpret_cast<const float4*>(A + (size_t)arow * KDIM + k0 + lc4);
            if (RELU_IN) {
                av.x = fmaxf(av.x, 0.0f); av.y = fmaxf(av.y, 0.0f);
                av.z = fmaxf(av.z, 0.0f); av.w = fmaxf(av.w, 0.0f);
            }
            __half2 h0 = __floats2half2_rn(av.x, av.y);
            __half2 h1 = __floats2half2_rn(av.z, av.w);
            uint2 u;
            u.x = *reinterpret_cast<uint32_t*>(&h0);
            u.y = *reinterpret_cast<uint32_t*>(&h1);
            *reinterpret_cast<uint2*>(As + lrow * ASTR + k0 + lc4) = u;
        }
    } else {
        const __half* A = (const __half*)Ain;
        const int lch = (tid & 1) * (KDIM / 2);
        const __half2 z2 = __float2half2_rn(0.0f);
#pragma unroll
        for (int k0 = 0; k0 < KDIM / 2; k0 += 8) {
            uint4 v = *reinterpret_cast<const uint4*>(A + (size_t)arow * KDIM + lch + k0);
            if (RELU_IN) {
                __half2* hv = reinterpret_cast<__half2*>(&v);
#pragma unroll
                for (int j = 0; j < 4; j++) hv[j] = __hmax2(hv[j], z2);
            }
            *reinterpret_cast<uint4*>(As + lrow * ASTR + lch + k0) = v;
        }
    }
    __syncthreads();

    float acc[8][4];
#pragma unroll
    for (int nt = 0; nt < 8; nt++)
#pragma unroll
        for (int j = 0; j < 4; j++) acc[nt][j] = 0.0f;

    const int r  = lane >> 2;
    const int c2 = (lane & 3) * 2;
    const __half* abase = As + (warp * 16 + r) * ASTR + c2;

#pragma unroll
    for (int ks = 0; ks < KDIM / 16; ks++) {
        const int k0 = ks * 16;
        uint32_t a0 = *reinterpret_cast<const uint32_t*>(abase + k0);
        uint32_t a1 = *reinterpret_cast<const uint32_t*>(abase + k0 + 8 * ASTR);
        uint32_t a2 = *reinterpret_cast<const uint32_t*>(abase + k0 + 8);
        uint32_t a3 = *reinterpret_cast<const uint32_t*>(abase + k0 + 8 * ASTR + 8);
        const uint2* bbase = Bf + ks * 256 + lane;
#pragma unroll
        for (int nt = 0; nt < 8; nt++) {
            uint2 b = bbase[nt * 32];
            mma_f16(acc[nt], a0, a1, a2, a3, b.x, b.y);
        }
    }

    const int mr0 = row0 + warp * 16 + r;
    const int mr1 = mr0 + 8;
    const float dv0 = (mr0 < M) ? g_dinv[mr0] : 0.0f;
    const float dv1 = (mr1 < M) ? g_dinv[mr1] : 0.0f;

#pragma unroll
    for (int nt = 0; nt < 8; nt++) {
        const int col = nt * 8 + c2;
        if (mr0 < M)
            hout[(size_t)mr0 * (HID / 2) + (col >> 1)] =
                __floats2half2_rn(acc[nt][0] * dv0, acc[nt][1] * dv0);
        if (mr1 < M)
            hout[(size_t)mr1 * (HID / 2) + (col >> 1)] =
                __floats2half2_rn(acc[nt][2] * dv1, acc[nt][3] * dv1);
    }
}

// ---------------------------------------------------------------------------
// Pull-mode aggregation: out[d] = bias + dinv[d] * (hh[d] + sum_{s in N(d)} hh[s])
// Self-loop seeded into accA; pure store epilogue (no RMW).
// 8 lanes/node; 16B fp16 gathers; two independent half-segment chains.
// ---------------------------------------------------------------------------
__device__ __forceinline__ void acc_16B(float2* acc, uint4 v) {
    float2 f0 = __half22float2(*reinterpret_cast<__half2*>(&v.x));
    float2 f1 = __half22float2(*reinterpret_cast<__half2*>(&v.y));
    float2 f2 = __half22float2(*reinterpret_cast<__half2*>(&v.z));
    float2 f3 = __half22float2(*reinterpret_cast<__half2*>(&v.w));
    acc[0].x += f0.x; acc[0].y += f0.y;
    acc[1].x += f1.x; acc[1].y += f1.y;
    acc[2].x += f2.x; acc[2].y += f2.y;
    acc[3].x += f3.x; acc[3].y += f3.y;
}

template<bool HALF_OUT>
__global__ void __launch_bounds__(256) k_node_agg(const __half2* __restrict__ hh,
                                                  const float* __restrict__ bias,
                                                  void* __restrict__ out,
                                                  int n)
{
    const int gid  = blockIdx.x * blockDim.x + threadIdx.x;
    const int node = gid >> 3;
    const int l    = gid & 7;
    if (node >= n) return;

    const int start = __ldg(&g_rowstart[node]);
    const int cn    = __ldg(&g_cnt[node]);
    const int half  = cn >> 1;

    float2 accA[4] = {{0,0},{0,0},{0,0},{0,0}};
    float2 accB[4] = {{0,0},{0,0},{0,0},{0,0}};

    // Self loop: seed accA with hh[node]
    {
        const uint4 v = __ldg(reinterpret_cast<const uint4*>(hh + (size_t)node * (HID / 2)) + l);
        acc_16B(accA, v);
    }

    const int a0 = start;
    const int b0 = start + half;
    for (int k = 0; k < half; k++) {
        const int sa = __ldg(&g_psrc[a0 + k]);
        const int sb = __ldg(&g_psrc[b0 + k]);
        const uint4 va = __ldg(reinterpret_cast<const uint4*>(hh + (size_t)sa * (HID / 2)) + l);
        const uint4 vb = __ldg(reinterpret_cast<const uint4*>(hh + (size_t)sb * (HID / 2)) + l);
        acc_16B(accA, va);
        acc_16B(accB, vb);
    }
    if (cn & 1) {
        const int s = __ldg(&g_psrc[start + cn - 1]);
        const uint4 v = __ldg(reinterpret_cast<const uint4*>(hh + (size_t)s * (HID / 2)) + l);
        acc_16B(accA, v);
    }

    const float dd = __ldg(&g_dinv[node]);
    const float4 bv0 = __ldg(reinterpret_cast<const float4*>(bias) + l * 2);
    const float4 bv1 = __ldg(reinterpret_cast<const float4*>(bias) + l * 2 + 1);

    float r0 = bv0.x + dd * (accA[0].x + accB[0].x);
    float r1 = bv0.y + dd * (accA[0].y + accB[0].y);
    float r2 = bv0.z + dd * (accA[1].x + accB[1].x);
    float r3 = bv0.w + dd * (accA[1].y + accB[1].y);
    float r4 = bv1.x + dd * (accA[2].x + accB[2].x);
    float r5 = bv1.y + dd * (accA[2].y + accB[2].y);
    float r6 = bv1.z + dd * (accA[3].x + accB[3].x);
    float r7 = bv1.w + dd * (accA[3].y + accB[3].y);

    if (HALF_OUT) {
        uint4 o;
        __half2* oh = reinterpret_cast<__half2*>(&o);
        oh[0] = __floats2half2_rn(r0, r1);
        oh[1] = __floats2half2_rn(r2, r3);
        oh[2] = __floats2half2_rn(r4, r5);
        oh[3] = __floats2half2_rn(r6, r7);
        *(reinterpret_cast<uint4*>((__half2*)out + (size_t)node * (HID / 2)) + l) = o;
    } else {
        float* p = (float*)out + (size_t)node * HID + l * 8;
        *reinterpret_cast<float4*>(p)     = make_float4(r0, r1, r2, r3);
        *reinterpret_cast<float4*>(p + 4) = make_float4(r4, r5, r6, r7);
    }
}

// ---------------------------------------------------------------------------
// Launch
// ---------------------------------------------------------------------------
extern "C" void kernel_launch(void* const* d_in, const int* in_sizes, int n_in,
                              void* d_out, int out_size)
{
    const float* x  = (const float*)d_in[0];
    const int*   ei = (const int*)d_in[1];   // edge_index is int32
    const float* W1 = (const float*)d_in[2];
    const float* b1 = (const float*)d_in[3];
    const float* W2 = (const float*)d_in[4];
    const float* b2 = (const float*)d_in[5];
    float* out = (float*)d_out;

    const int n  = in_sizes[0] / 128;
    const int nE = in_sizes[1] / 2;
    const int* src = ei;
    const int* dst = ei + nE;

    __half2 *hh = nullptr, *out1h = nullptr;
    uint2 *wf1 = nullptr, *wf2 = nullptr;
    cudaGetSymbolAddress((void**)&hh, g_hh);
    cudaGetSymbolAddress((void**)&out1h, g_out1h);
    cudaGetSymbolAddress((void**)&wf1, g_Wf1);
    cudaGetSymbolAddress((void**)&wf2, g_Wf2);

    const int nb_nodes = (n + 255) / 256;
    const int nb_edges = (nE + 255) / 256;
    const int nb_agg   = (n * 8 + 255) / 256;
    const int nb_gemm  = (n + 127) / 128;

    const int smem1 = 128 * ASTR * 2 + 8 * 256 * (int)sizeof(uint2);  // 51200
    const int smem2 = 128 * ASTR * 2 + 4 * 256 * (int)sizeof(uint2);  // 43008
    cudaFuncSetAttribute(k_gemm_hmma<128, false, false>,
                         cudaFuncAttributeMaxDynamicSharedMemorySize, smem1);
    cudaFuncSetAttribute(k_gemm_hmma<64, true, true>,
                         cudaFuncAttributeMaxDynamicSharedMemorySize, smem2);

    // Fused W packing + zeroing, then CSR build (count -> rowstart -> scatter)
    k_pack_zero<<<nb_nodes, 256>>>(W1, W2, n);
    k_count<<<nb_edges, 256>>>(dst, nE);
    k_rowstart<<<nb_nodes, 256>>>(n);
    k_scatter<<<nb_edges, 256>>>(src, dst, nE);

    // Layer 1: GEMM writes hh only; agg produces out1h = b1 + dinv*(self+neighbors)
    k_gemm_hmma<128, false, false><<<nb_gemm, 256, smem1>>>(x, wf1, hh, n);
    k_node_agg<true><<<nb_agg, 256>>>(hh, b1, out1h, n);

    // Layer 2: fp16 A input (ReLU fused on load); agg writes fp32 d_out directly
    k_gemm_hmma<64, true, true><<<nb_gemm, 256, smem2>>>(out1h, wf2, hh, n);
    k_node_agg<false><<<nb_agg, 256>>>(hh, b2, out, n);
}

// round 17
// speedup vs baseline: 1.4661x; 1.0168x over previous
#include <cuda_runtime.h>
#include <cuda_fp16.h>
#include <cstdint>

#define MAX_NODES 100000
#define MAX_EDGES 1250000
#define HID 64

// Scratch (allocation-free: __device__ globals)
__device__ int     g_cnt[MAX_NODES];
__device__ int     g_rowstart[MAX_NODES];
__device__ int     g_cursor[MAX_NODES];
__device__ int     g_total;
__device__ float   g_dinv[MAX_NODES];
__device__ int     g_psrc[MAX_EDGES];
__device__ __half2 g_hh[(size_t)MAX_NODES * (HID / 2)];    // dinv[s]*h[s], fp16 gather table
__device__ __half2 g_out1h[(size_t)MAX_NODES * (HID / 2)]; // layer-1 output, fp16
__device__ uint2   g_Wf1[8 * 8 * 32];   // W1 fragments
__device__ uint2   g_Wf2[4 * 8 * 32];   // W2 fragments

// ---------------------------------------------------------------------------
// Fused: pack W fragments (idx < 3072) + zero g_cnt (idx < n) + zero g_total
// ---------------------------------------------------------------------------
__global__ void k_pack_zero(const float* __restrict__ W1, const float* __restrict__ W2, int n) {
    int idx = blockIdx.x * blockDim.x + threadIdx.x;
    if (idx < n) g_cnt[idx] = 0;
    if (idx == 0) g_total = 0;
    if (idx < 3072) {
        const float* W;
        uint2* dstf;
        int rel;
        if (idx < 2048) { W = W1; dstf = g_Wf1; rel = idx; }
        else            { W = W2; dstf = g_Wf2; rel = idx - 2048; }
        const int lane  = rel & 31;
        const int nt    = (rel >> 5) & 7;
        const int kstep = rel >> 8;
        const int nn = nt * 8 + (lane >> 2);
        const int k0 = kstep * 16 + (lane & 3) * 2;
        __half2 b0 = __floats2half2_rn(__ldg(&W[(size_t)k0 * 64 + nn]),
                                       __ldg(&W[(size_t)(k0 + 1) * 64 + nn]));
        __half2 b1 = __floats2half2_rn(__ldg(&W[(size_t)(k0 + 8) * 64 + nn]),
                                       __ldg(&W[(size_t)(k0 + 9) * 64 + nn]));
        uint2 u;
        u.x = *reinterpret_cast<uint32_t*>(&b0);
        u.y = *reinterpret_cast<uint32_t*>(&b1);
        dstf[rel] = u;
    }
}

// ---------------------------------------------------------------------------
// CSR build: count -> rowstart (atomic bump, fused dinv+cursor) -> scatter
// ---------------------------------------------------------------------------
__global__ void k_count(const int* __restrict__ dst, int nE) {
    int e = blockIdx.x * blockDim.x + threadIdx.x;
    if (e < nE) atomicAdd(&g_cnt[__ldg(&dst[e])], 1);
}

__global__ void __launch_bounds__(256) k_rowstart(int n) {
    __shared__ int wsum[8];
    __shared__ int sbase;
    const int tid  = threadIdx.x;
    const int lane = tid & 31;
    const int wid  = tid >> 5;
    const int i = blockIdx.x * 256 + tid;

    int c = (i < n) ? g_cnt[i] : 0;
    int scan = c;
#pragma unroll
    for (int off = 1; off < 32; off <<= 1) {
        int v = __shfl_up_sync(0xffffffffu, scan, off);
        if (lane >= off) scan += v;
    }
    if (lane == 31) wsum[wid] = scan;
    __syncthreads();
    if (wid == 0) {
        int w = (lane < 8) ? wsum[lane] : 0;
        int ws = w;
#pragma unroll
        for (int off = 1; off < 8; off <<= 1) {
            int v = __shfl_up_sync(0xffffffffu, ws, off);
            if (lane >= off) ws += v;
        }
        if (lane < 8) wsum[lane] = ws - w;              // exclusive warp offsets
        if (lane == 7) sbase = atomicAdd(&g_total, ws); // ws @lane7 = block total
    }
    __syncthreads();
    if (i < n) {
        const int rs = sbase + wsum[wid] + scan - c;
        g_rowstart[i] = rs;
        g_cursor[i]   = rs;
        g_dinv[i]     = rsqrtf((float)c + 1.0f);
    }
}

__global__ void k_scatter(const int* __restrict__ src, const int* __restrict__ dst, int nE) {
    int e = blockIdx.x * blockDim.x + threadIdx.x;
    if (e < nE) {
        int d = __ldg(&dst[e]);
        int pos = atomicAdd(&g_cursor[d], 1);
        g_psrc[pos] = __ldg(&src[e]);
    }
}

// ---------------------------------------------------------------------------
// fp16 HMMA GEMM: h = act(A) @ W, mma.sync.m16n8k16 f32.f16.f16.f32.
// A fragments loaded DIRECTLY from global (each A element used exactly once;
// smem staging was pure overhead). B fragments staged in smem (heavy reuse).
// Output: hh = fp16(h*dinv) only (self+bias folded into agg).
// ---------------------------------------------------------------------------
__device__ __forceinline__ void mma_f16(float* c,
                                        uint32_t a0, uint32_t a1, uint32_t a2, uint32_t a3,
                                        uint32_t b0, uint32_t b1) {
    asm volatile("mma.sync.aligned.m16n8k16.row.col.f32.f16.f16.f32 "
                 "{%0,%1,%2,%3}, {%4,%5,%6,%7}, {%8,%9}, {%0,%1,%2,%3};"
                 : "+f"(c[0]), "+f"(c[1]), "+f"(c[2]), "+f"(c[3])
                 : "r"(a0), "r"(a1), "r"(a2), "r"(a3), "r"(b0), "r"(b1));
}

template<int KDIM, bool RELU_IN, bool IN_HALF>
__global__ void __launch_bounds__(256) k_gemm_hmma(const void* __restrict__ Ain,
                                                   const uint2* __restrict__ Wf,
                                                   __half2* __restrict__ hout,
                                                   int M)
{
    extern __shared__ char smem[];
    uint2* Bf = reinterpret_cast<uint2*>(smem);   // (KDIM/16)*256

    const int tid  = threadIdx.x;
    const int lane = tid & 31;
    const int warp = tid >> 5;
    const int row0 = blockIdx.x * 128;

    for (int i = tid; i < (KDIM / 16) * 256; i += 256) Bf[i] = Wf[i];

    const int r  = lane >> 2;
    const int c2 = (lane & 3) * 2;
    const int mr0 = row0 + warp * 16 + r;
    const int mr1 = mr0 + 8;
    const int ar0 = min(mr0, M - 1);
    const int ar1 = min(mr1, M - 1);

    __syncthreads();

    float acc[8][4];
#pragma unroll
    for (int nt = 0; nt < 8; nt++)
#pragma unroll
        for (int j = 0; j < 4; j++) acc[nt][j] = 0.0f;

#pragma unroll
    for (int ks = 0; ks < KDIM / 16; ks++) {
        const int k0 = ks * 16;
        uint32_t a0, a1, a2, a3;
        if (!IN_HALF) {
            const float* A = (const float*)Ain;
            float2 f0 = __ldg(reinterpret_cast<const float2*>(A + (size_t)ar0 * KDIM + k0 + c2));
            float2 f1 = __ldg(reinterpret_cast<const float2*>(A + (size_t)ar1 * KDIM + k0 + c2));
            float2 f2 = __ldg(reinterpret_cast<const float2*>(A + (size_t)ar0 * KDIM + k0 + 8 + c2));
            float2 f3 = __ldg(reinterpret_cast<const float2*>(A + (size_t)ar1 * KDIM + k0 + 8 + c2));
            if (RELU_IN) {
                f0.x = fmaxf(f0.x, 0.0f); f0.y = fmaxf(f0.y, 0.0f);
                f1.x = fmaxf(f1.x, 0.0f); f1.y = fmaxf(f1.y, 0.0f);
                f2.x = fmaxf(f2.x, 0.0f); f2.y = fmaxf(f2.y, 0.0f);
                f3.x = fmaxf(f3.x, 0.0f); f3.y = fmaxf(f3.y, 0.0f);
            }
            __half2 h0 = __floats2half2_rn(f0.x, f0.y);
            __half2 h1 = __floats2half2_rn(f1.x, f1.y);
            __half2 h2 = __floats2half2_rn(f2.x, f2.y);
            __half2 h3 = __floats2half2_rn(f3.x, f3.y);
            a0 = *reinterpret_cast<uint32_t*>(&h0);
            a1 = *reinterpret_cast<uint32_t*>(&h1);
            a2 = *reinterpret_cast<uint32_t*>(&h2);
            a3 = *reinterpret_cast<uint32_t*>(&h3);
        } else {
            const __half* A = (const __half*)Ain;
            a0 = __ldg(reinterpret_cast<const uint32_t*>(A + (size_t)ar0 * KDIM + k0 + c2));
            a1 = __ldg(reinterpret_cast<const uint32_t*>(A + (size_t)ar1 * KDIM + k0 + c2));
            a2 = __ldg(reinterpret_cast<const uint32_t*>(A + (size_t)ar0 * KDIM + k0 + 8 + c2));
            a3 = __ldg(reinterpret_cast<const uint32_t*>(A + (size_t)ar1 * KDIM + k0 + 8 + c2));
            if (RELU_IN) {
                const __half2 z2 = __float2half2_rn(0.0f);
                __half2 h0 = __hmax2(*reinterpret_cast<__half2*>(&a0), z2);
                __half2 h1 = __hmax2(*reinterpret_cast<__half2*>(&a1), z2);
                __half2 h2 = __hmax2(*reinterpret_cast<__half2*>(&a2), z2);
                __half2 h3 = __hmax2(*reinterpret_cast<__half2*>(&a3), z2);
                a0 = *reinterpret_cast<uint32_t*>(&h0);
                a1 = *reinterpret_cast<uint32_t*>(&h1);
                a2 = *reinterpret_cast<uint32_t*>(&h2);
                a3 = *reinterpret_cast<uint32_t*>(&h3);
            }
        }
        const uint2* bbase = Bf + ks * 256 + lane;
#pragma unroll
        for (int nt = 0; nt < 8; nt++) {
            uint2 b = bbase[nt * 32];
            mma_f16(acc[nt], a0, a1, a2, a3, b.x, b.y);
        }
    }

    const float dv0 = (mr0 < M) ? g_dinv[mr0] : 0.0f;
    const float dv1 = (mr1 < M) ? g_dinv[mr1] : 0.0f;

#pragma unroll
    for (int nt = 0; nt < 8; nt++) {
        const int col = nt * 8 + c2;
        if (mr0 < M)
            hout[(size_t)mr0 * (HID / 2) + (col >> 1)] =
                __floats2half2_rn(acc[nt][0] * dv0, acc[nt][1] * dv0);
        if (mr1 < M)
            hout[(size_t)mr1 * (HID / 2) + (col >> 1)] =
                __floats2half2_rn(acc[nt][2] * dv1, acc[nt][3] * dv1);
    }
}

// ---------------------------------------------------------------------------
// Pull-mode aggregation: out[d] = bias + dinv[d] * (hh[d] + sum_{s in N(d)} hh[s])
// Self-loop seeded into accA; pure store epilogue (no RMW).
// 8 lanes/node; 16B fp16 gathers; two independent half-segment chains.
// ---------------------------------------------------------------------------
__device__ __forceinline__ void acc_16B(float2* acc, uint4 v) {
    float2 f0 = __half22float2(*reinterpret_cast<__half2*>(&v.x));
    float2 f1 = __half22float2(*reinterpret_cast<__half2*>(&v.y));
    float2 f2 = __half22float2(*reinterpret_cast<__half2*>(&v.z));
    float2 f3 = __half22float2(*reinterpret_cast<__half2*>(&v.w));
    acc[0].x += f0.x; acc[0].y += f0.y;
    acc[1].x += f1.x; acc[1].y += f1.y;
    acc[2].x += f2.x; acc[2].y += f2.y;
    acc[3].x += f3.x; acc[3].y += f3.y;
}

template<bool HALF_OUT>
__global__ void __launch_bounds__(256) k_node_agg(const __half2* __restrict__ hh,
                                                  const float* __restrict__ bias,
                                                  void* __restrict__ out,
                                                  int n)
{
    const int gid  = blockIdx.x * blockDim.x + threadIdx.x;
    const int node = gid >> 3;
    const int l    = gid & 7;
    if (node >= n) return;

    const int start = __ldg(&g_rowstart[node]);
    const int cn    = __ldg(&g_cnt[node]);
    const int half  = cn >> 1;

    float2 accA[4] = {{0,0},{0,0},{0,0},{0,0}};
    float2 accB[4] = {{0,0},{0,0},{0,0},{0,0}};

    // Self loop: seed accA with hh[node]
    {
        const uint4 v = __ldg(reinterpret_cast<const uint4*>(hh + (size_t)node * (HID / 2)) + l);
        acc_16B(accA, v);
    }

    const int a0 = start;
    const int b0 = start + half;
    for (int k = 0; k < half; k++) {
        const int sa = __ldg(&g_psrc[a0 + k]);
        const int sb = __ldg(&g_psrc[b0 + k]);
        const uint4 va = __ldg(reinterpret_cast<const uint4*>(hh + (size_t)sa * (HID / 2)) + l);
        const uint4 vb = __ldg(reinterpret_cast<const uint4*>(hh + (size_t)sb * (HID / 2)) + l);
        acc_16B(accA, va);
        acc_16B(accB, vb);
    }
    if (cn & 1) {
        const int s = __ldg(&g_psrc[start + cn - 1]);
        const uint4 v = __ldg(reinterpret_cast<const uint4*>(hh + (size_t)s * (HID / 2)) + l);
        acc_16B(accA, v);
    }

    const float dd = __ldg(&g_dinv[node]);
    const float4 bv0 = __ldg(reinterpret_cast<const float4*>(bias) + l * 2);
    const float4 bv1 = __ldg(reinterpret_cast<const float4*>(bias) + l * 2 + 1);

    float r0 = bv0.x + dd * (accA[0].x + accB[0].x);
    float r1 = bv0.y + dd * (accA[0].y + accB[0].y);
    float r2 = bv0.z + dd * (accA[1].x + accB[1].x);
    float r3 = bv0.w + dd * (accA[1].y + accB[1].y);
    float r4 = bv1.x + dd * (accA[2].x + accB[2].x);
    float r5 = bv1.y + dd * (accA[2].y + accB[2].y);
    float r6 = bv1.z + dd * (accA[3].x + accB[3].x);
    float r7 = bv1.w + dd * (accA[3].y + accB[3].y);

    if (HALF_OUT) {
        uint4 o;
        __half2* oh = reinterpret_cast<__half2*>(&o);
        oh[0] = __floats2half2_rn(r0, r1);
        oh[1] = __floats2half2_rn(r2, r3);
        oh[2] = __floats2half2_rn(r4, r5);
        oh[3] = __floats2half2_rn(r6, r7);
        *(reinterpret_cast<uint4*>((__half2*)out + (size_t)node * (HID / 2)) + l) = o;
    } else {
        float* p = (float*)out + (size_t)node * HID + l * 8;
        *reinterpret_cast<float4*>(p)     = make_float4(r0, r1, r2, r3);
        *reinterpret_cast<float4*>(p + 4) = make_float4(r4, r5, r6, r7);
    }
}

// ---------------------------------------------------------------------------
// Launch
// ---------------------------------------------------------------------------
extern "C" void kernel_launch(void* const* d_in, const int* in_sizes, int n_in,
                              void* d_out, int out_size)
{
    const float* x  = (const float*)d_in[0];
    const int*   ei = (const int*)d_in[1];   // edge_index is int32
    const float* W1 = (const float*)d_in[2];
    const float* b1 = (const float*)d_in[3];
    const float* W2 = (const float*)d_in[4];
    const float* b2 = (const float*)d_in[5];
    float* out = (float*)d_out;

    const int n  = in_sizes[0] / 128;
    const int nE = in_sizes[1] / 2;
    const int* src = ei;
    const int* dst = ei + nE;

    __half2 *hh = nullptr, *out1h = nullptr;
    uint2 *wf1 = nullptr, *wf2 = nullptr;
    cudaGetSymbolAddress((void**)&hh, g_hh);
    cudaGetSymbolAddress((void**)&out1h, g_out1h);
    cudaGetSymbolAddress((void**)&wf1, g_Wf1);
    cudaGetSymbolAddress((void**)&wf2, g_Wf2);

    const int nb_nodes = (n + 255) / 256;
    const int nb_edges = (nE + 255) / 256;
    const int nb_agg   = (n * 8 + 255) / 256;
    const int nb_gemm  = (n + 127) / 128;

    const int smem1 = 8 * 256 * (int)sizeof(uint2);  // 16384 (B fragments only)
    const int smem2 = 4 * 256 * (int)sizeof(uint2);  // 8192
    cudaFuncSetAttribute(k_gemm_hmma<128, false, false>,
                         cudaFuncAttributeMaxDynamicSharedMemorySize, smem1);
    cudaFuncSetAttribute(k_gemm_hmma<64, true, true>,
                         cudaFuncAttributeMaxDynamicSharedMemorySize, smem2);

    // Fused W packing + zeroing, then CSR build (count -> rowstart -> scatter)
    k_pack_zero<<<nb_nodes, 256>>>(W1, W2, n);
    k_count<<<nb_edges, 256>>>(dst, nE);
    k_rowstart<<<nb_nodes, 256>>>(n);
    k_scatter<<<nb_edges, 256>>>(src, dst, nE);

    // Layer 1: GEMM writes hh only; agg produces out1h = b1 + dinv*(self+neighbors)
    k_gemm_hmma<128, false, false><<<nb_gemm, 256, smem1>>>(x, wf1, hh, n);
    k_node_agg<true><<<nb_agg, 256>>>(hh, b1, out1h, n);

    // Layer 2: fp16 A input (ReLU fused on load); agg writes fp32 d_out directly
    k_gemm_hmma<64, true, true><<<nb_gemm, 256, smem2>>>(out1h, wf2, hh, n);
    k_node_agg<false><<<nb_agg, 256>>>(hh, b2, out, n);
}